// round 7
// baseline (speedup 1.0000x reference)
#include <cuda_runtime.h>
#include <cuda_bf16.h>
#include <math.h>
#include <stdint.h>

#define BATCH 4
#define SEQ 1024
#define DIM 256
#define NH 8
#define DH 32
#define ROWS (BATCH*SEQ)      // 4096
#define MAXN 256
#define FFH 512
#define HD2 (NH*DIM)          // 2048

// ---------------- scratch ---------------------------------------------------------
__device__ float g_hp [ROWS*DIM];
__device__ float g_h  [ROWS*DIM];
__device__ float g_tmp[ROWS*DIM];
__device__ float g_ln [ROWS*DIM];
__device__ __nv_bfloat16 gA_hi[ROWS*HD2];
__device__ __nv_bfloat16 gA_lo[ROWS*HD2];
__device__ __nv_bfloat16 gF_hi[ROWS*FFH];
__device__ __nv_bfloat16 gF_lo[ROWS*FFH];
__device__ __nv_bfloat16 w0_hi[DIM*DIM],  w0_lo[DIM*DIM];
__device__ __nv_bfloat16 w1_hi[DIM*DIM],  w1_lo[DIM*DIM];
__device__ __nv_bfloat16 w2_hi[DIM*HD2],  w2_lo[DIM*HD2];
__device__ __nv_bfloat16 f1_hi[FFH*DIM],  f1_lo[FFH*DIM];
__device__ __nv_bfloat16 f2_hi[DIM*FFH],  f2_lo[DIM*FFH];
__device__ float g_va_src[NH*DIM];
__device__ float g_va_dst[NH*DIM];
__device__ float g_src [ROWS*NH];
__device__ float g_dst [ROWS*NH];
__device__ float g_src2[ROWS*NH];
__device__ float g_dst2[ROWS*NH];
__device__ int   g_nbr[ROWS*MAXN];
__device__ int   g_cnt[ROWS];

// ---------------- helpers ---------------------------------------------------------
__device__ __forceinline__ uint32_t smem_u32(const void* p){
    uint32_t a;
    asm("{ .reg .u64 t; cvta.to.shared.u64 t, %1; cvt.u32.u64 %0, t; }" : "=r"(a) : "l"(p));
    return a;
}
__device__ __forceinline__ void split_val(float v, __nv_bfloat16& hi, __nv_bfloat16& lo){
    hi = __float2bfloat16(v);
    lo = __float2bfloat16(v - __bfloat162float(hi));
}
#define CPA16(dst, src) \
    asm volatile("cp.async.cg.shared.global [%0], [%1], 16;" :: "r"(dst), "l"(src) : "memory")
#define LDSM4(r0,r1,r2,r3,addr) \
    asm volatile("ldmatrix.sync.aligned.m8n8.x4.shared.b16 {%0,%1,%2,%3}, [%4];" \
        : "=r"(r0),"=r"(r1),"=r"(r2),"=r"(r3) : "r"(addr))

__device__ __forceinline__ void mma_bf16(float* c, const uint32_t* a, uint32_t b0, uint32_t b1){
    asm volatile("mma.sync.aligned.m16n8k16.row.col.f32.bf16.bf16.f32 "
        "{%0,%1,%2,%3}, {%4,%5,%6,%7}, {%8,%9}, {%0,%1,%2,%3};"
        : "+f"(c[0]),"+f"(c[1]),"+f"(c[2]),"+f"(c[3])
        : "r"(a[0]),"r"(a[1]),"r"(a[2]),"r"(a[3]), "r"(b0),"r"(b1));
}

// ---------------- HMMA split-bf16 GEMM, TM=64/TN=64, 3-stage, 3 CTAs/SM -----------
// EPI: 0 plain; 1 +bias GELU -> bf16 split; 2 +bias+res; 3 +res; 4 plain + fused head scores
template<int EPI>
__global__ __launch_bounds__(256)
void gemm_mma(const __nv_bfloat16* __restrict__ Ah, const __nv_bfloat16* __restrict__ Al,
              const __nv_bfloat16* __restrict__ Bh, const __nv_bfloat16* __restrict__ Bl,
              const float* __restrict__ bias, const float* __restrict__ res,
              const float* __restrict__ asv, const float* __restrict__ adv,
              float* __restrict__ C, __nv_bfloat16* __restrict__ Chi, __nv_bfloat16* __restrict__ Clo,
              int M, int N, int K){
    constexpr int LD   = 40;
    constexpr int A_SZ = 64*LD*2;            // 5120 B per matrix per stage
    constexpr int B_SZ = 64*LD*2;
    constexpr int BUF  = 2*A_SZ + 2*B_SZ;    // 20480
    extern __shared__ char sm[];
    uint32_t sb = smem_u32(sm);
    int tid = threadIdx.x, lane = tid & 31, wid = tid >> 5;
    int bm = blockIdx.y*64, bn = blockIdx.x*64;
    int wm = (wid & 3)*16, wn = (wid >> 2)*32;   // 4 m-warps x 2 n-warps, warp tile 16x32
    float acc[4][4] = {};
    int nch = K >> 5;

    // per-thread load coords (one 16B vector per matrix per stage)
    int lrow = tid >> 2, lc8 = (tid & 3)*8;
    uint32_t lso = (uint32_t)(lrow*LD + lc8)*2;

    auto load_chunk = [&](int c){
        uint32_t s0 = sb + (c % 3)*BUF;
        int k0 = c*32;
        size_t ga = (size_t)(bm + lrow)*K + k0 + lc8;
        size_t gb = (size_t)(bn + lrow)*K + k0 + lc8;
        CPA16(s0 + lso,                Ah + ga);
        CPA16(s0 + A_SZ + lso,         Al + ga);
        CPA16(s0 + 2*A_SZ + lso,       Bh + gb);
        CPA16(s0 + 2*A_SZ + B_SZ + lso, Bl + gb);
        asm volatile("cp.async.commit_group;" ::: "memory");
    };

    load_chunk(0);
    load_chunk(1);
    for (int c = 0; c < nch; c++){
        if (c + 2 < nch){
            load_chunk(c + 2);
            asm volatile("cp.async.wait_group 2;" ::: "memory");
        } else if (c + 1 < nch){
            asm volatile("cp.async.wait_group 1;" ::: "memory");
        } else {
            asm volatile("cp.async.wait_group 0;" ::: "memory");
        }
        __syncthreads();
        uint32_t sA = sb + (c % 3)*BUF;
        uint32_t sB = sA + 2*A_SZ;
        #pragma unroll
        for (int kk = 0; kk < 32; kk += 16){
            uint32_t ah[4], al[4];
            uint32_t ad = sA + (uint32_t)(((wm + (lane & 15))*LD + kk + (lane >> 4)*8)*2);
            LDSM4(ah[0],ah[1],ah[2],ah[3], ad);
            LDSM4(al[0],al[1],al[2],al[3], ad + A_SZ);
            #pragma unroll
            for (int p = 0; p < 2; p++){
                uint32_t bd = sB + (uint32_t)(((wn + p*16 + ((lane >> 4) << 3) + (lane & 7))*LD
                                              + kk + ((lane >> 3) & 1)*8)*2);
                uint32_t bh[4], bl[4];
                LDSM4(bh[0],bh[1],bh[2],bh[3], bd);
                LDSM4(bl[0],bl[1],bl[2],bl[3], bd + B_SZ);
                #pragma unroll
                for (int j = 0; j < 2; j++){
                    float* a_ = acc[p*2 + j];
                    mma_bf16(a_, ah, bh[2*j], bh[2*j+1]);
                    mma_bf16(a_, ah, bl[2*j], bl[2*j+1]);
                    mma_bf16(a_, al, bh[2*j], bh[2*j+1]);
                }
            }
        }
        __syncthreads();
    }

    // epilogue
    int g = lane >> 2, tg = lane & 3;
    float ca[8], cd[8];
    float sacc[2] = {}, dacc[2] = {};
    int hidx = 0;
    if (EPI == 4){
        hidx = (bn + wn) >> 5;        // warp tile spans exactly one 32-ch head
        #pragma unroll
        for (int nb = 0; nb < 4; nb++)
            #pragma unroll
            for (int e = 0; e < 2; e++){
                int chi = nb*8 + tg*2 + e;
                ca[nb*2+e] = asv[hidx*DH + chi];
                cd[nb*2+e] = adv[hidx*DH + chi];
            }
    }
    #pragma unroll
    for (int nb = 0; nb < 4; nb++){
        float* a_ = acc[nb];
        int col = bn + wn + nb*8 + tg*2;
        #pragma unroll
        for (int half = 0; half < 2; half++){
            int r = bm + wm + g + half*8;
            size_t ci = (size_t)r*N + col;
            float v0 = a_[half*2], v1 = a_[half*2+1];
            if (EPI == 0 || EPI == 4){
                *(float2*)&C[ci] = make_float2(v0, v1);
                if (EPI == 4){
                    sacc[half] = fmaf(v0, ca[nb*2], fmaf(v1, ca[nb*2+1], sacc[half]));
                    dacc[half] = fmaf(v0, cd[nb*2], fmaf(v1, cd[nb*2+1], dacc[half]));
                }
            } else if (EPI == 1){
                v0 += bias[col]; v1 += bias[col+1];
                float t0 = 0.7978845608028654f*(v0 + 0.044715f*v0*v0*v0);
                v0 = 0.5f*v0*(1.f + tanhf(t0));
                float t1 = 0.7978845608028654f*(v1 + 0.044715f*v1*v1*v1);
                v1 = 0.5f*v1*(1.f + tanhf(t1));
                __nv_bfloat16 h0,l0,h1,l1;
                split_val(v0,h0,l0); split_val(v1,h1,l1);
                __nv_bfloat162 hp2; hp2.x=h0; hp2.y=h1;
                __nv_bfloat162 lp2; lp2.x=l0; lp2.y=l1;
                *(__nv_bfloat162*)&Chi[ci] = hp2;
                *(__nv_bfloat162*)&Clo[ci] = lp2;
            } else if (EPI == 2){
                float2 rr = *(const float2*)&res[ci];
                *(float2*)&C[ci] = make_float2(v0 + bias[col] + rr.x, v1 + bias[col+1] + rr.y);
            } else {
                float2 rr = *(const float2*)&res[ci];
                *(float2*)&C[ci] = make_float2(v0 + rr.x, v1 + rr.y);
            }
        }
    }
    if (EPI == 4){
        #pragma unroll
        for (int half = 0; half < 2; half++){
            float s = sacc[half], d = dacc[half];
            s += __shfl_xor_sync(0xffffffffu, s, 1);
            s += __shfl_xor_sync(0xffffffffu, s, 2);
            d += __shfl_xor_sync(0xffffffffu, d, 1);
            d += __shfl_xor_sync(0xffffffffu, d, 2);
            if (tg == 0){
                int r = bm + wm + g + half*8;
                g_src[r*NH + hidx] = s;
                g_dst[r*NH + hidx] = d;
            }
        }
    }
}

// ---------------- merged prep: transposes + split_x + va + build_nbr --------------
__device__ __forceinline__ void trans_tile(const float* __restrict__ inp, int ldi,
                                           __nv_bfloat16* __restrict__ oh, __nv_bfloat16* __restrict__ ol,
                                           int ldo, int kt, int nt, float scale){
    __shared__ float tile[32][33];
    int tx = threadIdx.x & 31, ty0 = threadIdx.x >> 5;
    #pragma unroll
    for (int i = 0; i < 4; i++){
        int ty = ty0 + i*8;
        tile[ty][tx] = inp[(size_t)(kt*32 + ty)*ldi + nt*32 + tx];
    }
    __syncthreads();
    #pragma unroll
    for (int i = 0; i < 4; i++){
        int ty = ty0 + i*8;
        float v = scale * tile[tx][ty];
        size_t oi = (size_t)(nt*32 + ty)*ldo + kt*32 + tx;
        __nv_bfloat16 hi, lo; split_val(v, hi, lo);
        oh[oi] = hi; ol[oi] = lo;
    }
}

__global__ __launch_bounds__(256)
void prep(const float* __restrict__ W0, const float* __restrict__ W1, const float* __restrict__ W2,
          const float* __restrict__ F1, const float* __restrict__ F2,
          const float* __restrict__ x,
          const float* __restrict__ as2, const float* __restrict__ ad2,
          const float* __restrict__ adj){
    int b = blockIdx.x, tid = threadIdx.x;
    if (b < 64){
        trans_tile(W0, DIM, w0_hi, w0_lo, DIM, b >> 3, b & 7, 1.f);
    } else if (b < 128){
        int t = b - 64;
        trans_tile(W1, DIM, w1_hi, w1_lo, DIM, t >> 3, t & 7, 1.f);
    } else if (b < 640){
        int rel = b - 128, h = rel >> 6, t = rel & 63;
        trans_tile(W2 + h*DIM, HD2, w2_hi + h*DIM, w2_lo + h*DIM, HD2, t >> 3, t & 7, 0.125f);
    } else if (b < 768){
        int rel = b - 640;
        trans_tile(F1, FFH, f1_hi, f1_lo, DIM, rel >> 4, rel & 15, 1.f);
    } else if (b < 896){
        int rel = b - 768;
        trans_tile(F2, DIM, f2_hi, f2_lo, FFH, rel >> 3, rel & 7, 1.f);
    } else if (b < 1920){
        int idx4 = (b - 896)*256 + tid;
        float4 v = *(const float4*)&x[idx4*4];
        __nv_bfloat16 h0,l0,h1,l1,h2,l2,h3,l3;
        split_val(v.x,h0,l0); split_val(v.y,h1,l1);
        split_val(v.z,h2,l2); split_val(v.w,h3,l3);
        __nv_bfloat162 ha; ha.x=h0; ha.y=h1;
        __nv_bfloat162 hb; hb.x=h2; hb.y=h3;
        __nv_bfloat162 la; la.x=l0; la.y=l1;
        __nv_bfloat162 lb; lb.x=l2; lb.y=l3;
        *(__nv_bfloat162*)&gA_hi[idx4*4]   = ha;
        *(__nv_bfloat162*)&gA_hi[idx4*4+2] = hb;
        *(__nv_bfloat162*)&gA_lo[idx4*4]   = la;
        *(__nv_bfloat162*)&gA_lo[idx4*4+2] = lb;
    } else if (b < 2176){
        int rel = b - 1920;
        int gw = rel*8 + (tid >> 5);
        int lane = tid & 31;
        int h = gw >> 8, c = gw & 255;
        float s = 0.f, t = 0.f;
        #pragma unroll
        for (int d = lane; d < DIM; d += 32){
            float wv = W2[(size_t)c*HD2 + h*DIM + d];
            s += wv * as2[h*DIM + d];
            t += wv * ad2[h*DIM + d];
        }
        #pragma unroll
        for (int o = 16; o > 0; o >>= 1){
            s += __shfl_down_sync(0xffffffffu, s, o);
            t += __shfl_down_sync(0xffffffffu, t, o);
        }
        if (lane == 0){ g_va_src[h*DIM + c] = s; g_va_dst[h*DIM + c] = t; }
    } else {
        int row = (b - 2176)*8 + (tid >> 5);
        int lane = tid & 31;
        const float* arow = adj + (size_t)row * SEQ;
        int cnt = 0;
        for (int base = 0; base < SEQ; base += 128){
            float vv[4];
            #pragma unroll
            for (int i = 0; i < 4; i++) vv[i] = arow[base + i*32 + lane];
            #pragma unroll
            for (int i = 0; i < 4; i++){
                bool p = vv[i] > 0.f;
                unsigned m = __ballot_sync(0xffffffffu, p);
                if (p){
                    int pos = cnt + __popc(m & ((1u << lane) - 1u));
                    if (pos < MAXN) g_nbr[row*MAXN + pos] = base + i*32 + lane;
                }
                cnt += __popc(m);
            }
        }
        if (lane == 0) g_cnt[row] = cnt < MAXN ? cnt : MAXN;
    }
}

// ---------------- softmax weights -------------------------------------------------
__device__ __forceinline__ void compute_weights(int row, int b, int cnt,
                                                const int* nbr, float* w, float* srcI,
                                                const float* __restrict__ srcA,
                                                const float* __restrict__ dstA){
    int tid = threadIdx.x;
    if (tid < NH) srcI[tid] = srcA[row*NH + tid];
    __syncthreads();
    for (int idx = tid; idx < cnt*NH; idx += 256){
        int n = idx >> 3, h = idx & 7;
        float e = srcI[h] + dstA[(size_t)(b*SEQ + nbr[n])*NH + h];
        w[n*NH + h] = e > 0.f ? e : 0.2f*e;
    }
    __syncthreads();
    int h = tid >> 5, lane = tid & 31;
    float m = -1e30f;
    for (int n = lane; n < cnt; n += 32) m = fmaxf(m, w[n*NH + h]);
    #pragma unroll
    for (int o = 16; o > 0; o >>= 1) m = fmaxf(m, __shfl_xor_sync(0xffffffffu, m, o));
    float ssum = 0.f;
    for (int n = lane; n < cnt; n += 32){
        float e = expf(w[n*NH + h] - m);
        w[n*NH + h] = e;
        ssum += e;
    }
    #pragma unroll
    for (int o = 16; o > 0; o >>= 1) ssum += __shfl_xor_sync(0xffffffffu, ssum, o);
    float inv = 1.f / ssum;
    for (int n = lane; n < cnt; n += 32) w[n*NH + h] *= inv;
    __syncthreads();
}

// aggregate + residual + ELU (+optionally fused layer-2 scores)
template<bool S2>
__global__ __launch_bounds__(256)
void attn01(const float* __restrict__ resid, float* __restrict__ out){
    int row = blockIdx.x;
    int b = row / SEQ;
    int tid = threadIdx.x;
    int cnt = g_cnt[row];
    __shared__ int   nbr[MAXN];
    __shared__ float w[MAXN*NH];
    __shared__ float srcI[NH];
    __shared__ float val[DIM];
    for (int n = tid; n < cnt; n += 256) nbr[n] = g_nbr[row*MAXN + n];
    __syncthreads();
    compute_weights(row, b, cnt, nbr, w, srcI, g_src, g_dst);
    int ch = tid;
    int hh = ch >> 5;
    float acc = 0.f;
    int n = 0;
    for (; n + 4 <= cnt; n += 4){
        int j0 = nbr[n], j1 = nbr[n+1], j2 = nbr[n+2], j3 = nbr[n+3];
        float v0 = g_hp[((size_t)(b*SEQ + j0))*DIM + ch];
        float v1 = g_hp[((size_t)(b*SEQ + j1))*DIM + ch];
        float v2 = g_hp[((size_t)(b*SEQ + j2))*DIM + ch];
        float v3 = g_hp[((size_t)(b*SEQ + j3))*DIM + ch];
        acc = fmaf(w[(n+0)*NH + hh], v0, acc);
        acc = fmaf(w[(n+1)*NH + hh], v1, acc);
        acc = fmaf(w[(n+2)*NH + hh], v2, acc);
        acc = fmaf(w[(n+3)*NH + hh], v3, acc);
    }
    for (; n < cnt; n++)
        acc = fmaf(w[n*NH + hh], g_hp[((size_t)(b*SEQ + nbr[n]))*DIM + ch], acc);
    size_t oi = (size_t)row*DIM + ch;
    float v = acc + resid[oi];
    v = v > 0.f ? v : expm1f(v);
    out[oi] = v;
    split_val(v, gA_hi[oi], gA_lo[oi]);
    if (S2){
        val[ch] = v;
        __syncthreads();
        int h = tid >> 5, lane = tid & 31;
        float s = 0.f, t = 0.f;
        #pragma unroll
        for (int d = lane; d < DIM; d += 32){
            float vd = val[d];
            s = fmaf(vd, g_va_src[h*DIM + d], s);
            t = fmaf(vd, g_va_dst[h*DIM + d], t);
        }
        #pragma unroll
        for (int o = 16; o > 0; o >>= 1){
            s += __shfl_down_sync(0xffffffffu, s, o);
            t += __shfl_down_sync(0xffffffffu, t, o);
        }
        if (lane == 0){ g_src2[row*NH + h] = s; g_dst2[row*NH + h] = t; }
    }
}

// layer 2: aggregate h per head
__global__ __launch_bounds__(256)
void attn2b(){
    int row = blockIdx.x;
    int b = row / SEQ;
    int tid = threadIdx.x;
    int cnt = g_cnt[row];
    __shared__ int   nbr[MAXN];
    __shared__ float w[MAXN*NH];
    __shared__ float srcI[NH];
    for (int n = tid; n < cnt; n += 256) nbr[n] = g_nbr[row*MAXN + n];
    __syncthreads();
    compute_weights(row, b, cnt, nbr, w, srcI, g_src2, g_dst2);
    int c = tid;
    float acc[NH] = {};
    int n = 0;
    for (; n + 2 <= cnt; n += 2){
        int j0 = nbr[n], j1 = nbr[n+1];
        float v0 = g_h[(size_t)(b*SEQ + j0)*DIM + c];
        float v1 = g_h[(size_t)(b*SEQ + j1)*DIM + c];
        const float* w0p = &w[n*NH];
        const float* w1p = &w[(n+1)*NH];
        #pragma unroll
        for (int h = 0; h < NH; h++){
            acc[h] = fmaf(w0p[h], v0, acc[h]);
            acc[h] = fmaf(w1p[h], v1, acc[h]);
        }
    }
    for (; n < cnt; n++){
        float v = g_h[(size_t)(b*SEQ + nbr[n])*DIM + c];
        const float* wp = &w[n*NH];
        #pragma unroll
        for (int h = 0; h < NH; h++) acc[h] = fmaf(wp[h], v, acc[h]);
    }
    #pragma unroll
    for (int h = 0; h < NH; h++){
        size_t oi = (size_t)row*HD2 + h*DIM + c;
        split_val(acc[h], gA_hi[oi], gA_lo[oi]);
    }
}

// ---------------- LayerNorm -------------------------------------------------------
__global__ void layernorm(const float* __restrict__ in,
                          const float* __restrict__ ln_g, const float* __restrict__ ln_b,
                          float* __restrict__ out){
    int row = blockIdx.x, tid = threadIdx.x;
    float v = in[(size_t)row*DIM + tid];
    __shared__ float red[8];
    __shared__ float mu, rstd;
    float s = v;
    #pragma unroll
    for (int o = 16; o > 0; o >>= 1) s += __shfl_xor_sync(0xffffffffu, s, o);
    if ((tid & 31) == 0) red[tid >> 5] = s;
    __syncthreads();
    if (tid == 0){ float t = 0.f; for (int i = 0; i < 8; i++) t += red[i]; mu = t / 256.f; }
    __syncthreads();
    float d = v - mu;
    s = d*d;
    #pragma unroll
    for (int o = 16; o > 0; o >>= 1) s += __shfl_xor_sync(0xffffffffu, s, o);
    if ((tid & 31) == 0) red[tid >> 5] = s;
    __syncthreads();
    if (tid == 0){ float t = 0.f; for (int i = 0; i < 8; i++) t += red[i]; rstd = rsqrtf(t/256.f + 1e-5f); }
    __syncthreads();
    size_t oi = (size_t)row*DIM + tid;
    float o = d*rstd*ln_g[tid] + ln_b[tid];
    out[oi] = o;
    split_val(o, gA_hi[oi], gA_lo[oi]);
}

// ---------------- launch ---------------------------------------------------------
extern "C" void kernel_launch(void* const* d_in, const int* in_sizes, int n_in,
                              void* d_out, int out_size){
    const float* adj    = (const float*)d_in[0];
    const float* x      = (const float*)d_in[1];
    const float* W0     = (const float*)d_in[2];
    const float* a_src0 = (const float*)d_in[3];
    const float* a_dst0 = (const float*)d_in[4];
    const float* W1     = (const float*)d_in[5];
    const float* a_src1 = (const float*)d_in[6];
    const float* a_dst1 = (const float*)d_in[7];
    const float* W2     = (const float*)d_in[8];
    const float* a_src2 = (const float*)d_in[9];
    const float* a_dst2 = (const float*)d_in[10];
    const float* ln_g   = (const float*)d_in[11];
    const float* ln_b   = (const float*)d_in[12];
    const float* ff_w1  = (const float*)d_in[13];
    const float* ff_b1  = (const float*)d_in[14];
    const float* ff_w2  = (const float*)d_in[15];
    const float* ff_b2  = (const float*)d_in[16];
    float* out = (float*)d_out;

    float *p_hp, *p_h, *p_tmp, *p_ln;
    __nv_bfloat16 *pAh, *pAl, *pFh, *pFl;
    __nv_bfloat16 *pw0h,*pw0l,*pw1h,*pw1l,*pw2h,*pw2l,*pf1h,*pf1l,*pf2h,*pf2l;
    cudaGetSymbolAddress((void**)&p_hp,  g_hp);
    cudaGetSymbolAddress((void**)&p_h,   g_h);
    cudaGetSymbolAddress((void**)&p_tmp, g_tmp);
    cudaGetSymbolAddress((void**)&p_ln,  g_ln);
    cudaGetSymbolAddress((void**)&pAh, gA_hi);  cudaGetSymbolAddress((void**)&pAl, gA_lo);
    cudaGetSymbolAddress((void**)&pFh, gF_hi);  cudaGetSymbolAddress((void**)&pFl, gF_lo);
    cudaGetSymbolAddress((void**)&pw0h, w0_hi); cudaGetSymbolAddress((void**)&pw0l, w0_lo);
    cudaGetSymbolAddress((void**)&pw1h, w1_hi); cudaGetSymbolAddress((void**)&pw1l, w1_lo);
    cudaGetSymbolAddress((void**)&pw2h, w2_hi); cudaGetSymbolAddress((void**)&pw2l, w2_lo);
    cudaGetSymbolAddress((void**)&pf1h, f1_hi); cudaGetSymbolAddress((void**)&pf1l, f1_lo);
    cudaGetSymbolAddress((void**)&pf2h, f2_hi); cudaGetSymbolAddress((void**)&pf2l, f2_lo);

    const int SMB = 3*20480;   // 61440 B -> 3 CTAs/SM
    cudaFuncSetAttribute(gemm_mma<4>, cudaFuncAttributeMaxDynamicSharedMemorySize, SMB);
    cudaFuncSetAttribute(gemm_mma<3>, cudaFuncAttributeMaxDynamicSharedMemorySize, SMB);
    cudaFuncSetAttribute(gemm_mma<2>, cudaFuncAttributeMaxDynamicSharedMemorySize, SMB);
    cudaFuncSetAttribute(gemm_mma<1>, cudaFuncAttributeMaxDynamicSharedMemorySize, SMB);

    dim3 blk(256);
    prep<<<2688, blk>>>(W0, W1, W2, ff_w1, ff_w2, x, a_src2, a_dst2, adj);

    // ---- GAT layer 0 (GEMM + fused scores) ----
    gemm_mma<4><<<dim3(4,64), blk, SMB>>>(pAh, pAl, pw0h, pw0l, nullptr, nullptr,
                                          a_src0, a_dst0, p_hp, nullptr, nullptr, ROWS, DIM, DIM);
    attn01<false><<<ROWS, blk>>>(x, p_h);

    // ---- GAT layer 1 (GEMM + fused scores; attn also emits layer-2 scores) ----
    gemm_mma<4><<<dim3(4,64), blk, SMB>>>(pAh, pAl, pw1h, pw1l, nullptr, nullptr,
                                          a_src1, a_dst1, p_hp, nullptr, nullptr, ROWS, DIM, DIM);
    attn01<true><<<ROWS, blk>>>(p_h, p_h);

    // ---- GAT layer 2 ----
    attn2b<<<ROWS, blk>>>();
    gemm_mma<3><<<dim3(4,64), blk, SMB>>>(pAh, pAl, pw2h, pw2l, nullptr, p_h,
                                          nullptr, nullptr, p_tmp, nullptr, nullptr, ROWS, DIM, HD2);

    // ---- LayerNorm ----
    layernorm<<<ROWS, blk>>>(p_tmp, ln_g, ln_b, p_ln);

    // ---- FFN ----
    gemm_mma<1><<<dim3(8,64), blk, SMB>>>(pAh, pAl, pf1h, pf1l, ff_b1, nullptr,
                                          nullptr, nullptr, nullptr, pFh, pFl, ROWS, FFH, DIM);
    gemm_mma<2><<<dim3(4,64), blk, SMB>>>(pFh, pFl, pf2h, pf2l, ff_b2, p_ln,
                                          nullptr, nullptr, out, nullptr, nullptr, ROWS, DIM, FFH);
}